// round 17
// baseline (speedup 1.0000x reference)
#include <cuda_runtime.h>

#define NUM_BINS  512
#define NUM_NODES 128
#define N_PAIRS   1024
#define K_ELEMS   16384
#define NREP      16            // hist replicas: 32KB table
#define LREP      8             // lookup: 8 float2 replicas -> same 32KB buffer

#define TASKS_PER_PAIR 8
#define CHUNK_F4   512          // float4 per task (2048 elems)
#define TOTAL_TASKS (N_PAIRS * TASKS_PER_PAIR)   // 8192
#define GRID       592          // 148 SMs * 4 CTAs = exactly one wave (required!)

// Scratch (allocation-free rule: __device__ globals, zero-initialized at load)
__device__ float g_hist[NUM_NODES * NUM_BINS];
__device__ float g_cdf[NUM_NODES * NUM_BINS];
// 2-byte lookup code per element: bin index if valid, 0xFFFF sentinel if not.
__device__ unsigned short g_code[(size_t)N_PAIRS * K_ELEMS];
// grid-barrier state (self-resetting each launch -> graph-replay safe)
__device__ unsigned g_bar_ctr;
__device__ unsigned g_fin_ctr;

extern __shared__ float sh_dyn[];   // 32 KB, reused across phases

// Device-wide barrier. SAFE ONLY because the grid is exactly one fully
// co-resident wave (GRID=592 @ 4 CTAs/SM enforced by launch bounds + smem).
__device__ __forceinline__ void grid_barrier(unsigned target) {
    __syncthreads();
    if (threadIdx.x == 0) {
        __threadfence();
        atomicAdd(&g_bar_ctr, 1u);
        while (*(volatile unsigned*)&g_bar_ctr < target)
            __nanosleep(64);
    }
    __syncthreads();
}

// ---------------------------------------------------------------------------
// ONE persistent kernel: Phase A hist -> barrier -> Phase B cdf -> barrier ->
// Phase C lookup. Removes two kernel-boundary wave drain/fill gaps (~2.1us).
// ---------------------------------------------------------------------------
__global__ void __launch_bounds__(512, 4) fused_kernel(
    const float* __restrict__ res, const float* __restrict__ wgt,
    const int* __restrict__ src, const int* __restrict__ dst,
    float* __restrict__ out)
{
    const int tid  = threadIdx.x;
    const int lane = tid & 31;

    // ======================= Phase A: histogram + codes ====================
    {
        float* tab = sh_dyn;          // NUM_BINS * NREP floats = 32 KB
        const int rep = (lane + ((lane >> 4) << 3)) & 15;   // conflict-free

        float4* shz = (float4*)tab;
        #pragma unroll
        for (int i = 0; i < (NUM_BINS * NREP / 4) / 512; i++)
            shz[tid + i * 512] = make_float4(0.f, 0.f, 0.f, 0.f);
        __syncthreads();

        int lo = (int)(((long long)blockIdx.x       * TOTAL_TASKS) / GRID);
        int hi = (int)(((long long)(blockIdx.x + 1) * TOTAL_TASKS) / GRID);

        int t = lo;
        while (t < hi) {
            const int p    = t / TASKS_PER_PAIR;
            const int tend = min(hi, (p + 1) * TASKS_PER_PAIR);

            const float4* r4 = (const float4*)(res + (size_t)p * K_ELEMS);
            const float4* w4 = (const float4*)(wgt + (size_t)p * K_ELEMS);
            ushort4* c4 = (ushort4*)(g_code + (size_t)p * K_ELEMS);

            const int i0 = (t    - p * TASKS_PER_PAIR) * CHUNK_F4;
            const int i1 = (tend - p * TASKS_PER_PAIR) * CHUNK_F4;

            for (int i = i0 + tid; i < i1; i += 512) {
                float4 rv = __ldcs(&r4[i]);   // read-once: stream past L2
                float4 wv = __ldcs(&w4[i]);
                float rr[4] = {rv.x, rv.y, rv.z, rv.w};
                float ww[4] = {wv.x, wv.y, wv.z, wv.w};
                unsigned short cc[4];
                #pragma unroll
                for (int j = 0; j < 4; j++) {
                    float x = rr[j] * 512.0f;             // *2^9 exact
                    int b  = min(__float2int_rd(x), NUM_BINS - 1);
                    atomicAdd(&tab[b * NREP + rep], ww[j]);   // conflict-free
                    int b2 = __float2int_rd(x + 0.5f);
                    bool valid = ((unsigned)b2 < NUM_BINS) && (ww[j] > 0.0f);
                    cc[j] = valid ? (unsigned short)b2 : (unsigned short)0xFFFFu;
                }
                c4[i] = make_ushort4(cc[0], cc[1], cc[2], cc[3]);
            }
            __syncthreads();

            // vectorized reduce: 16 replicas -> 1 per bin, zero behind read
            const int bin = tid;
            float4* t4 = (float4*)(tab + bin * NREP);
            float h = 0.0f;
            #pragma unroll
            for (int k = 0; k < 4; k++) {
                int c = (k + (bin >> 1)) & 3;
                float4 v = t4[c];
                h += (v.x + v.y) + (v.z + v.w);
                t4[c] = make_float4(0.f, 0.f, 0.f, 0.f);
            }

            const int s = src[p];
            const int d = dst[p];
            atomicAdd(&g_hist[s * NUM_BINS + bin], h);
            atomicAdd(&g_hist[d * NUM_BINS + bin], h);
            __syncthreads();

            t = tend;
        }
    }

    grid_barrier(GRID);            // all g_hist atomics complete

    // ======================= Phase B: cdf (blocks 0..127) ==================
    if (blockIdx.x < NUM_NODES) {
        __shared__ float warp_sums[16];
        __shared__ float inv_total;

        const int node = blockIdx.x;

        float h = __ldcg(&g_hist[node * NUM_BINS + tid]);   // L2-coherent read
        g_hist[node * NUM_BINS + tid] = 0.0f;               // reset for replay
        float x = h;

        #pragma unroll
        for (int o = 1; o < 32; o <<= 1) {
            float y = __shfl_up_sync(0xffffffffu, x, o);
            if ((tid & 31) >= o) x += y;
        }
        if ((tid & 31) == 31) warp_sums[tid >> 5] = x;
        __syncthreads();

        if (tid < 16) {
            float s = warp_sums[tid];
            #pragma unroll
            for (int o = 1; o < 16; o <<= 1) {
                float y = __shfl_up_sync(0x0000ffffu, s, o);
                if (tid >= o) s += y;
            }
            warp_sums[tid] = s;
            if (tid == 15) inv_total = 1.0f / (s + 1e-10f);  // total == tw
        }
        __syncthreads();

        float base = (tid >= 32) ? warp_sums[(tid >> 5) - 1] : 0.0f;
        g_cdf[node * NUM_BINS + tid] = (x + base) * inv_total;
    }

    grid_barrier(2 * GRID);        // g_cdf complete

    // ======================= Phase C: lookup ===============================
    {
        float2* tab = (float2*)sh_dyn;    // NUM_BINS * LREP float2 = 32 KB
        const int laneL = tid & (LREP - 1);

        int lo = (int)(((long long)blockIdx.x       * TOTAL_TASKS) / GRID);
        int hi = (int)(((long long)(blockIdx.x + 1) * TOTAL_TASKS) / GRID);

        int t = lo;
        while (t < hi) {
            const int p    = t / TASKS_PER_PAIR;
            const int tend = min(hi, (p + 1) * TASKS_PER_PAIR);

            __syncthreads();   // previous segment's smem readers are done
            const int s = src[p];
            const int d = dst[p];
            {
                float2 v = make_float2(__ldcg(&g_cdf[s * NUM_BINS + tid]),
                                       __ldcg(&g_cdf[d * NUM_BINS + tid]));
                #pragma unroll
                for (int r = 0; r < LREP; r++)      // stagger: conflict-free
                    tab[tid * LREP + ((r + tid) & (LREP - 1))] = v;
            }
            __syncthreads();

            const ushort4* c4 = (const ushort4*)(g_code + (size_t)p * K_ELEMS);
            float4* o_s = (float4*)(out + (size_t)p * K_ELEMS);
            float4* o_d = (float4*)(out + (size_t)(N_PAIRS + p) * K_ELEMS);

            const int i0 = (t    - p * TASKS_PER_PAIR) * CHUNK_F4;
            const int i1 = (tend - p * TASKS_PER_PAIR) * CHUNK_F4;

            ushort4 cv = c4[i0 + tid];              // depth-1 prefetch
            for (int i = i0 + tid; i < i1; i += 512) {
                ushort4 cn;
                if (i + 512 < i1) cn = c4[i + 512];
                unsigned short cc[4] = {cv.x, cv.y, cv.z, cv.w};
                float4 os, od;
                float* pos = (float*)&os;
                float* pod = (float*)&od;
                #pragma unroll
                for (int j = 0; j < 4; j++) {
                    unsigned short c = cc[j];
                    if (c < NUM_BINS) {
                        float2 v = tab[(int)c * LREP + laneL];
                        pos[j] = v.x;
                        pod[j] = v.y;
                    } else {
                        pos[j] = 2.0f;
                        pod[j] = 2.0f;
                    }
                }
                __stcs(&o_s[i], os);   // streaming store (load-bearing!)
                __stcs(&o_d[i], od);
                cv = cn;
            }

            t = tend;
        }
    }

    // ---- self-reset of barrier state (last block to finish resets) --------
    __syncthreads();
    if (tid == 0) {
        unsigned old = atomicAdd(&g_fin_ctr, 1u);
        if (old == GRID - 1) {
            g_bar_ctr = 0;     // all blocks already past both barriers
            g_fin_ctr = 0;
            __threadfence();
        }
    }
}

// ---------------------------------------------------------------------------
extern "C" void kernel_launch(void* const* d_in, const int* in_sizes, int n_in,
                              void* d_out, int out_size)
{
    const float* res = (const float*)d_in[0];
    const float* wgt = (const float*)d_in[1];
    const int*   src = (const int*)d_in[2];
    const int*   dst = (const int*)d_in[3];
    float*       out = (float*)d_out;

    const int smem = NUM_BINS * NREP * sizeof(float);   // 32 KB (reused)
    cudaFuncSetAttribute(fused_kernel,
                         cudaFuncAttributeMaxDynamicSharedMemorySize, smem);

    fused_kernel<<<GRID, 512, smem>>>(res, wgt, src, dst, out);
}